// round 16
// baseline (speedup 1.0000x reference)
#include <cuda_runtime.h>
#include <cuda_bf16.h>
#include <cstdint>

#define BN_EPS 1e-5f

static constexpr size_t SZ64 = (size_t)16 * 256 * 64 * 64;
static constexpr size_t SZ32 = (size_t)16 * 256 * 32 * 32;

__device__ float g_A64[SZ64];
__device__ float g_B32a[SZ32];
__device__ float g_B32b[SZ32];
__device__ float g_B32c[SZ32];
__device__ float g_mean[256];
__device__ float g_r[256];
__device__ float g_cnorm[512];
__device__ int   g_q[16384];

// ---------------- portable tensor-core helpers (sm_80+ PTX, legal on sm_103) --------
__device__ __forceinline__ uint32_t smem_u32(const void* p) {
    uint32_t a;
    asm("{ .reg .u64 t; cvta.to.shared.u64 t, %1; cvt.u32.u64 %0, t; }" : "=r"(a) : "l"(p));
    return a;
}
__device__ __forceinline__ void ldsm4(uint32_t* r, uint32_t addr) {
    asm volatile("ldmatrix.sync.aligned.m8n8.x4.shared.b16 {%0,%1,%2,%3}, [%4];"
                 : "=r"(r[0]), "=r"(r[1]), "=r"(r[2]), "=r"(r[3]) : "r"(addr));
}
__device__ __forceinline__ void ldsm2(uint32_t* r, uint32_t addr) {
    asm volatile("ldmatrix.sync.aligned.m8n8.x2.shared.b16 {%0,%1}, [%2];"
                 : "=r"(r[0]), "=r"(r[1]) : "r"(addr));
}
__device__ __forceinline__ void mma16816(float* d, const uint32_t* a, const uint32_t* b) {
    asm volatile(
        "mma.sync.aligned.m16n8k16.row.col.f32.bf16.bf16.f32 "
        "{%0,%1,%2,%3}, {%4,%5,%6,%7}, {%8,%9}, {%0,%1,%2,%3};"
        : "+f"(d[0]), "+f"(d[1]), "+f"(d[2]), "+f"(d[3])
        : "r"(a[0]), "r"(a[1]), "r"(a[2]), "r"(a[3]), "r"(b[0]), "r"(b[1]));
}

// ---- BN batch stats: mean + r = 1/sqrt(var+eps), jnp.var two-pass semantics ----
__global__ void bn_stats_kernel(const float* __restrict__ x,
                                float* __restrict__ mean_out,
                                float* __restrict__ r_out,
                                int N, int C, int HW)
{
    int c = blockIdx.x;
    int tx = threadIdx.x;
    __shared__ float red[256];
    __shared__ float s_m;
    float inv = 1.f / (float)(N * HW);

    float s = 0.f;
    for (int n = 0; n < N; ++n) {
        const float* p = x + ((size_t)n * C + c) * HW;
        for (int i = tx; i < HW; i += 256) s += p[i];
    }
    red[tx] = s;
    __syncthreads();
    for (int o = 128; o > 0; o >>= 1) {
        if (tx < o) red[tx] += red[tx + o];
        __syncthreads();
    }
    if (tx == 0) s_m = red[0] * inv;
    __syncthreads();
    float m = s_m;

    float s2 = 0.f;
    for (int n = 0; n < N; ++n) {
        const float* p = x + ((size_t)n * C + c) * HW;
        for (int i = tx; i < HW; i += 256) {
            float d = __fsub_rn(p[i], m);
            s2 += __fmul_rn(d, d);
        }
    }
    red[tx] = s2;
    __syncthreads();
    for (int o = 128; o > 0; o >>= 1) {
        if (tx < o) red[tx] += red[tx + o];
        __syncthreads();
    }
    if (tx == 0) {
        float var = red[0] * inv;
        mean_out[c] = m;
        r_out[c] = __fdiv_rn(1.0f, __fsqrt_rn(__fadd_rn(var, BN_EPS)));
    }
}

__device__ __forceinline__ float bnrelu_apply(float v, float m, float r, float g, float b)
{
    float t = __fsub_rn(v, m);
    t = __fmul_rn(t, r);
    t = __fmul_rn(t, g);
    t = __fadd_rn(t, b);
    return fmaxf(t, 0.f);
}

// ============ DECODER resblock convs via mma.sync bf16 2-split (x_rec path) =========
// Block: 128 co x 64 px (one image, 2 oh rows). 8 warps, 4(M)x2(N) grid of 32x32
// warp tiles. K chunks of 32 staged K-major, row stride 40 bf16 (ldmatrix-friendly).
template<bool IS3X3, bool ADDRES>
__global__ void __launch_bounds__(256)
conv_mma(const float* __restrict__ in, const float* __restrict__ wgt,
         const float* __restrict__ bias,
         const float* __restrict__ bmean, const float* __restrict__ br,
         const float* __restrict__ bg, const float* __restrict__ bb,
         const float* __restrict__ res, float* __restrict__ out)
{
    constexpr int KTOT = IS3X3 ? 2304 : 256;
    constexpr int NCH  = KTOT / 32;
    constexpr int AST  = 40;   // bf16 row stride (80B: 16B-aligned, bank-distinct)
    __shared__ __nv_bfloat16 sAh[128 * AST], sAl[128 * AST];
    __shared__ __nv_bfloat16 sBh[64 * AST],  sBl[64 * AST];

    int tx = threadIdx.x, wid = tx >> 5, lane = tx & 31;
    int n = blockIdx.x >> 4, pxt = blockIdx.x & 15;
    int oh0 = pxt * 2;
    int co0 = blockIdx.y * 128;
    int wm = (wid >> 1) * 32;    // warp co base
    int wn = (wid & 1) * 32;     // warp px base

    uint32_t bAh = smem_u32(sAh), bAl = smem_u32(sAl);
    uint32_t bBh = smem_u32(sBh), bBl = smem_u32(sBl);

    float d[2][4][4];
#pragma unroll
    for (int mi = 0; mi < 2; ++mi)
#pragma unroll
        for (int ni = 0; ni < 4; ++ni)
#pragma unroll
            for (int e = 0; e < 4; ++e) d[mi][ni][e] = 0.f;

#pragma unroll 1
    for (int c = 0; c < NCH; ++c) {
        __syncthreads();
        // stage A (weights) 128co x 32k, hi+lo
#pragma unroll 1
        for (int idx = tx; idx < 4096; idx += 256) {
            int co = idx >> 5, j = idx & 31, k = c * 32 + j;
            float w;
            if (IS3X3) {
                int ci = k / 9, t = k - ci * 9;
                w = wgt[((size_t)(co0 + co) * 256 + ci) * 9 + t];
            } else {
                w = wgt[(size_t)(co0 + co) * 256 + k];
            }
            __nv_bfloat16 h = __float2bfloat16(w);
            __nv_bfloat16 l = __float2bfloat16(__fsub_rn(w, __bfloat162float(h)));
            sAh[co * AST + j] = h;
            sAl[co * AST + j] = l;
        }
        // stage B (activations/im2col) 64px x 32k, hi+lo
#pragma unroll 1
        for (int idx = tx; idx < 2048; idx += 256) {
            int p = idx >> 5, j = idx & 31, k = c * 32 + j;
            int oh = oh0 + (p >> 5), ow = p & 31;
            float v = 0.f;
            if (IS3X3) {
                int ci = k / 9, t = k - ci * 9, kh = t / 3, kw = t - kh * 3;
                int ih = oh + kh - 1, iw = ow + kw - 1;
                if ((unsigned)ih < 32u && (unsigned)iw < 32u) {
                    v = in[(((size_t)n * 256 + ci) * 32 + ih) * 32 + iw];
                    v = bnrelu_apply(v, bmean[ci], br[ci], bg[ci], bb[ci]);
                }
            } else {
                v = in[(((size_t)n * 256 + k) * 32 + oh) * 32 + ow];
                v = bnrelu_apply(v, bmean[k], br[k], bg[k], bb[k]);
            }
            __nv_bfloat16 h = __float2bfloat16(v);
            __nv_bfloat16 l = __float2bfloat16(__fsub_rn(v, __bfloat162float(h)));
            sBh[p * AST + j] = h;
            sBl[p * AST + j] = l;
        }
        __syncthreads();
#pragma unroll
        for (int ks = 0; ks < 2; ++ks) {
            int k0 = ks * 16;
            uint32_t Ah[2][4], Al[2][4], Bh[4][2], Bl[4][2];
            int arow = lane & 15;
            int akof = k0 + (lane >> 4) * 8;
#pragma unroll
            for (int mi = 0; mi < 2; ++mi) {
                uint32_t off = (uint32_t)((wm + mi * 16 + arow) * AST + akof) * 2;
                ldsm4(Ah[mi], bAh + off);
                ldsm4(Al[mi], bAl + off);
            }
            int brow = lane & 7;
            int bkof = k0 + ((lane >> 3) & 1) * 8;
#pragma unroll
            for (int ni = 0; ni < 4; ++ni) {
                uint32_t off = (uint32_t)((wn + ni * 8 + brow) * AST + bkof) * 2;
                ldsm2(Bh[ni], bBh + off);
                ldsm2(Bl[ni], bBl + off);
            }
#pragma unroll
            for (int mi = 0; mi < 2; ++mi)
#pragma unroll
                for (int ni = 0; ni < 4; ++ni) {
                    mma16816(d[mi][ni], Ah[mi], Bh[ni]);
                    mma16816(d[mi][ni], Ah[mi], Bl[ni]);
                    mma16816(d[mi][ni], Al[mi], Bh[ni]);
                }
        }
    }
    // epilogue: d[mi][ni] thread mapping (standard m16n8):
    //   e0:(row,col) e1:(row,col+1) e2:(row+8,col) e3:(row+8,col+1)
    int r0 = lane >> 2, cpair = 2 * (lane & 3);
#pragma unroll
    for (int mi = 0; mi < 2; ++mi) {
#pragma unroll
        for (int ni = 0; ni < 4; ++ni) {
            int row = wm + mi * 16 + r0;
            int col = wn + ni * 8 + cpair;
            int oh = oh0 + (col >> 5), ow = col & 31;
            int coA = co0 + row, coB = co0 + row + 8;
            float bvA = bias[coA], bvB = bias[coB];
            size_t pA = (((size_t)n * 256 + coA) * 32 + oh) * 32 + ow;
            size_t pB = (((size_t)n * 256 + coB) * 32 + oh) * 32 + ow;
            float v0 = __fadd_rn(d[mi][ni][0], bvA);
            float v1 = __fadd_rn(d[mi][ni][1], bvA);
            float v2 = __fadd_rn(d[mi][ni][2], bvB);
            float v3 = __fadd_rn(d[mi][ni][3], bvB);
            if (ADDRES) {
                v0 = __fadd_rn(v0, res[pA]);
                v1 = __fadd_rn(v1, res[pA + 1]);
                v2 = __fadd_rn(v2, res[pB]);
                v3 = __fadd_rn(v3, res[pB + 1]);
            }
            out[pA]     = v0;
            out[pA + 1] = v1;
            out[pB]     = v2;
            out[pB + 1] = v3;
        }
    }
}

// ================= ENCODER conv 3x3 (exact fp32, unchanged) =================
__global__ void __launch_bounds__(256)
conv3x3_v2(const float* __restrict__ in, const float* __restrict__ wgt,
           const float* __restrict__ bias,
           const float* __restrict__ bmean, const float* __restrict__ br,
           const float* __restrict__ bg, const float* __restrict__ bb,
           float* __restrict__ out)
{
    constexpr int CI = 8, KC = 72, WS = 73, PH = 10, PW = 18;
    __shared__ float s_in[CI * PH * PW];
    __shared__ float s_w[32 * WS];

    int n   = blockIdx.x >> 3;
    int t   = blockIdx.x & 7;
    int oh0 = (t >> 1) * 8, ow0 = (t & 1) * 16;
    int co0 = blockIdx.y * 32;
    int tx = threadIdx.x, c = tx & 15, r = tx >> 4;
    int row = r >> 1, owl0 = (r & 1) * 8;

    float acc[2][8];
#pragma unroll
    for (int j = 0; j < 2; ++j)
#pragma unroll
        for (int p = 0; p < 8; ++p) acc[j][p] = 0.f;

    int ihb = oh0 - 1, iwb = ow0 - 1;

#pragma unroll 1
    for (int ci0 = 0; ci0 < 256; ci0 += CI) {
        __syncthreads();
#pragma unroll 1
        for (int idx = tx; idx < CI * PH * PW; idx += 256) {
            int ci = idx / (PH * PW);
            int rem = idx - ci * (PH * PW);
            int lh = rem / PW, lw = rem - lh * PW;
            int ih = ihb + lh, iw = iwb + lw;
            int cg = ci0 + ci;
            float v = 0.f;
            if ((unsigned)ih < 32u && (unsigned)iw < 32u) {
                v = in[(((size_t)n * 256 + cg) * 32 + ih) * 32 + iw];
                v = bnrelu_apply(v, bmean[cg], br[cg], bg[cg], bb[cg]);
            }
            s_in[idx] = v;
        }
#pragma unroll 1
        for (int idx = tx; idx < 32 * KC; idx += 256) {
            int co = idx / KC, k = idx - co * KC;
            int ci = k / 9, kk = k - ci * 9;
            s_w[co * WS + k] = wgt[((size_t)(co0 + co) * 256 + ci0 + ci) * 9 + kk];
        }
        __syncthreads();
#pragma unroll
        for (int ci = 0; ci < CI; ++ci) {
#pragma unroll
            for (int kh = 0; kh < 3; ++kh) {
                const float* bp = &s_in[ci * PH * PW + (row + kh) * PW + owl0];
                float v[10];
#pragma unroll
                for (int q = 0; q < 5; ++q) {
                    float2 Q = *(const float2*)(bp + 2 * q);
                    v[2 * q] = Q.x; v[2 * q + 1] = Q.y;
                }
                int kbase = ci * 9 + kh * 3;
#pragma unroll
                for (int kw = 0; kw < 3; ++kw) {
                    int k = kbase + kw;
                    float wv[2];
#pragma unroll
                    for (int j = 0; j < 2; ++j) wv[j] = s_w[(c + 16 * j) * WS + k];
#pragma unroll
                    for (int j = 0; j < 2; ++j)
#pragma unroll
                        for (int p = 0; p < 8; ++p)
                            acc[j][p] = fmaf(wv[j], v[kw + p], acc[j][p]);
                }
            }
        }
    }
    int oh = oh0 + row;
#pragma unroll
    for (int j = 0; j < 2; ++j) {
        int co = co0 + c + 16 * j;
        float bv = bias[co];
        size_t base = (((size_t)n * 256 + co) * 32 + oh) * 32 + ow0 + owl0;
#pragma unroll
        for (int p = 0; p < 8; ++p)
            out[base + p] = __fadd_rn(acc[j][p], bv);
    }
}

// ================= ENCODER conv 1x1 (exact fp32, unchanged) =================
__global__ void __launch_bounds__(256)
conv1x1_v2(const float* __restrict__ in, const float* __restrict__ wgt,
           const float* __restrict__ bias,
           const float* __restrict__ bmean, const float* __restrict__ br,
           const float* __restrict__ bg, const float* __restrict__ bb,
           const float* __restrict__ res, float* __restrict__ out)
{
    constexpr int CI = 32, WS = 33;
    __shared__ float s_in[CI * 128];
    __shared__ float s_w[64 * WS];

    int n   = blockIdx.x >> 3;
    int t   = blockIdx.x & 7;
    int oh0 = (t >> 1) * 8, ow0 = (t & 1) * 16;
    int co0 = blockIdx.y * 64;
    int tx = threadIdx.x, c = tx & 15, r = tx >> 4;
    int row = r >> 1, owl0 = (r & 1) * 8;

    float acc[4][8];
#pragma unroll
    for (int j = 0; j < 4; ++j)
#pragma unroll
        for (int p = 0; p < 8; ++p) acc[j][p] = 0.f;

#pragma unroll 1
    for (int ci0 = 0; ci0 < 256; ci0 += CI) {
        __syncthreads();
#pragma unroll 1
        for (int idx = tx; idx < CI * 128; idx += 256) {
            int ci = idx >> 7, rem = idx & 127;
            int ih = oh0 + (rem >> 4), iw = ow0 + (rem & 15);
            int cg = ci0 + ci;
            float v = in[(((size_t)n * 256 + cg) * 32 + ih) * 32 + iw];
            s_in[idx] = bnrelu_apply(v, bmean[cg], br[cg], bg[cg], bb[cg]);
        }
#pragma unroll 1
        for (int idx = tx; idx < 64 * CI; idx += 256) {
            int co = idx / CI, k = idx - co * CI;
            s_w[co * WS + k] = wgt[(size_t)(co0 + co) * 256 + ci0 + k];
        }
        __syncthreads();
#pragma unroll 4
        for (int ci = 0; ci < CI; ++ci) {
            const float* bp = &s_in[ci * 128 + row * 16 + owl0];
            float v[8];
#pragma unroll
            for (int q = 0; q < 4; ++q) {
                float2 Q = *(const float2*)(bp + 2 * q);
                v[2 * q] = Q.x; v[2 * q + 1] = Q.y;
            }
            float wv[4];
#pragma unroll
            for (int j = 0; j < 4; ++j) wv[j] = s_w[(c + 16 * j) * WS + ci];
#pragma unroll
            for (int j = 0; j < 4; ++j)
#pragma unroll
                for (int p = 0; p < 8; ++p)
                    acc[j][p] = fmaf(wv[j], v[p], acc[j][p]);
        }
    }
    int oh = oh0 + row;
#pragma unroll
    for (int j = 0; j < 4; ++j) {
        int co = co0 + c + 16 * j;
        float bv = bias[co];
        size_t base = (((size_t)n * 256 + co) * 32 + oh) * 32 + ow0 + owl0;
#pragma unroll
        for (int p = 0; p < 8; ++p)
            out[base + p] = __fadd_rn(__fadd_rn(acc[j][p], bv), res[base + p]);
    }
}

// ================= conv 4x4 s2 p1 (ec1/ec2, exact fp32) =================
template<bool BNRELU>
__global__ void __launch_bounds__(256)
conv4x4s2_v2(const float* __restrict__ in, const float* __restrict__ wgt,
             const float* __restrict__ bias,
             const float* __restrict__ bmean, const float* __restrict__ br,
             const float* __restrict__ bg, const float* __restrict__ bb,
             float* __restrict__ out,
             int N, int Cin, int Hin, int Win, int Cout, int Hout, int Wout)
{
    constexpr int CI = 4, KC = 64, WS = 65, PH = 18, PW = 34;
    __shared__ float s_in[CI * PH * PW];
    __shared__ float s_w[32 * WS];

    int tilesW = Wout / 16, tilesH = Hout / 8;
    int tpi = tilesW * tilesH;
    int n = blockIdx.x / tpi;
    int t = blockIdx.x % tpi;
    int oh0 = (t / tilesW) * 8, ow0 = (t % tilesW) * 16;
    int co0 = blockIdx.y * 32;
    int tx = threadIdx.x, c = tx & 15, r = tx >> 4;
    int row = r >> 1, owl0 = (r & 1) * 8;

    float acc[2][8];
#pragma unroll
    for (int j = 0; j < 2; ++j)
#pragma unroll
        for (int p = 0; p < 8; ++p) acc[j][p] = 0.f;

    int ihb = oh0 * 2 - 1, iwb = ow0 * 2 - 1;

#pragma unroll 1
    for (int ci0 = 0; ci0 < Cin; ci0 += CI) {
        __syncthreads();
#pragma unroll 1
        for (int idx = tx; idx < CI * PH * PW; idx += 256) {
            int ci = idx / (PH * PW);
            int rem = idx - ci * (PH * PW);
            int lh = rem / PW, lw = rem - lh * PW;
            int ih = ihb + lh, iw = iwb + lw;
            int cg = ci0 + ci;
            float v = 0.f;
            if (cg < Cin && (unsigned)ih < (unsigned)Hin && (unsigned)iw < (unsigned)Win) {
                v = in[(((size_t)n * Cin + cg) * Hin + ih) * Win + iw];
                if (BNRELU) v = bnrelu_apply(v, bmean[cg], br[cg], bg[cg], bb[cg]);
            }
            s_in[idx] = v;
        }
#pragma unroll 1
        for (int idx = tx; idx < 32 * KC; idx += 256) {
            int co = idx / KC, k = idx - co * KC;
            int ci = k >> 4, kk = k & 15;
            int cg = ci0 + ci;
            s_w[co * WS + k] = (cg < Cin) ? wgt[((size_t)(co0 + co) * Cin + cg) * 16 + kk] : 0.f;
        }
        __syncthreads();
#pragma unroll
        for (int ci = 0; ci < CI; ++ci) {
#pragma unroll
            for (int kh = 0; kh < 4; ++kh) {
                const float* bp = &s_in[ci * PH * PW + (row * 2 + kh) * PW + owl0 * 2];
                float v[18];
#pragma unroll
                for (int q = 0; q < 9; ++q) {
                    float2 Q = *(const float2*)(bp + 2 * q);
                    v[2 * q] = Q.x; v[2 * q + 1] = Q.y;
                }
#pragma unroll
                for (int kw = 0; kw < 4; ++kw) {
                    int k = ci * 16 + kh * 4 + kw;
                    float wv[2];
#pragma unroll
                    for (int j = 0; j < 2; ++j) wv[j] = s_w[(c + 16 * j) * WS + k];
#pragma unroll
                    for (int j = 0; j < 2; ++j)
#pragma unroll
                        for (int p = 0; p < 8; ++p)
                            acc[j][p] = fmaf(wv[j], v[kw + 2 * p], acc[j][p]);
                }
            }
        }
    }
    int oh = oh0 + row;
#pragma unroll
    for (int j = 0; j < 2; ++j) {
        int co = co0 + c + 16 * j;
        float bv = bias[co];
        size_t base = (((size_t)n * Cout + co) * Hout + oh) * Wout + ow0 + owl0;
#pragma unroll
        for (int p = 0; p < 8; ++p)
            out[base + p] = __fadd_rn(acc[j][p], bv);
    }
}

// ================= transposed conv 4x4 s2 p1 (decoder, fp32) =================
__global__ void __launch_bounds__(256)
convT4x4_v2(const float* __restrict__ in, const float* __restrict__ wgt,
            const float* __restrict__ bias,
            const float* __restrict__ bmean, const float* __restrict__ br,
            const float* __restrict__ bg, const float* __restrict__ bb,
            float* __restrict__ out,
            int N, int Cin, int Hin, int Win, int Cout, int Hout, int Wout)
{
    constexpr int CI = 4, KC = 64, WS = 65, PH = 6, PW = 10;
    __shared__ float s_in[CI * PH * PW + 2];
    __shared__ float s_w[64 * WS];

    int tilesW = Wout / 16, tilesH = Hout / 8;
    int tpi = tilesW * tilesH;
    int n = blockIdx.x / tpi;
    int t = blockIdx.x % tpi;
    int oh0 = (t / tilesW) * 8, ow0 = (t % tilesW) * 16;
    int co0 = blockIdx.y * 64;
    int tx = threadIdx.x, c = tx & 15, r = tx >> 4;
    int row = r >> 1, par = r & 1;

    int ih0 = (oh0 >> 1) - 1, iw0 = (ow0 >> 1) - 1;
    int khp = (row + 1) & 1;
    int kwp = 1 - par;

    float acc[4][8];
#pragma unroll
    for (int j = 0; j < 4; ++j)
#pragma unroll
        for (int p = 0; p < 8; ++p) acc[j][p] = 0.f;

#pragma unroll 1
    for (int ci0 = 0; ci0 < Cin; ci0 += CI) {
        __syncthreads();
#pragma unroll 1
        for (int idx = tx; idx < CI * PH * PW; idx += 256) {
            int ci = idx / (PH * PW);
            int rem = idx - ci * (PH * PW);
            int lh = rem / PW, lw = rem - lh * PW;
            int ih = ih0 + lh, iw = iw0 + lw;
            int cg = ci0 + ci;
            float v = 0.f;
            if ((unsigned)ih < (unsigned)Hin && (unsigned)iw < (unsigned)Win) {
                v = in[(((size_t)n * Cin + cg) * Hin + ih) * Win + iw];
                v = bnrelu_apply(v, bmean[cg], br[cg], bg[cg], bb[cg]);
            }
            s_in[idx] = v;
        }
#pragma unroll 1
        for (int idx = tx; idx < 64 * KC; idx += 256) {
            int co = idx / KC, k = idx - co * KC;
            int ci = k >> 4, kk = k & 15;
            s_w[co * WS + k] = wgt[(((size_t)(ci0 + ci) * Cout + co0 + co) << 4) + kk];
        }
        __syncthreads();
#pragma unroll
        for (int ci = 0; ci < CI; ++ci) {
#pragma unroll
            for (int a = 0; a < 2; ++a) {
                int kh  = khp + 2 * a;
                int ihl = ((row + 1) >> 1) + 1 - a;
                int s   = ci * PH * PW + ihl * PW + par;
                int e   = s & ~1;
                int o   = s - e;
                float v[10];
#pragma unroll
                for (int q = 0; q < 5; ++q) {
                    float2 Q = *(const float2*)(&s_in[e + 2 * q]);
                    v[2 * q] = Q.x; v[2 * q + 1] = Q.y;
                }
#pragma unroll
                for (int b = 0; b < 2; ++b) {
                    int kw = kwp + 2 * b;
                    int k  = ci * 16 + kh * 4 + kw;
                    float wv[4];
#pragma unroll
                    for (int j = 0; j < 4; ++j) wv[j] = s_w[(c + 16 * j) * WS + k];
#pragma unroll
                    for (int j = 0; j < 4; ++j)
#pragma unroll
                        for (int p = 0; p < 8; ++p)
                            acc[j][p] = fmaf(wv[j], v[o + 1 - b + p], acc[j][p]);
                }
            }
        }
    }
    int oh = oh0 + row;
#pragma unroll
    for (int j = 0; j < 4; ++j) {
        int co = co0 + c + 16 * j;
        float bv = bias[co];
        size_t base = (((size_t)n * Cout + co) * Hout + oh) * Wout + ow0 + par;
#pragma unroll
        for (int p = 0; p < 8; ++p)
            out[base + 2 * p] = __fadd_rn(acc[j][p], bv);
    }
}

// ---------------- final transposed conv to 3 channels ----------------
__global__ void __launch_bounds__(256)
convT_out_kernel(const float* __restrict__ in, const float* __restrict__ wgt,
                 const float* __restrict__ bias,
                 const float* __restrict__ bmean, const float* __restrict__ br,
                 const float* __restrict__ bg, const float* __restrict__ bb,
                 float* __restrict__ out,
                 int N, int Cin, int Hin, int Win, int Hout, int Wout)
{
    constexpr int CI = 16;
    __shared__ float s_in[CI * 100];
    __shared__ float s_w[CI * 48];
    int tilesW = Wout / 16;
    int tpi = tilesW * (Hout / 16);
    int n  = blockIdx.x / tpi;
    int t  = blockIdx.x % tpi;
    int oh0 = (t / tilesW) * 16, ow0 = (t % tilesW) * 16;
    int tx  = threadIdx.x;
    int row = tx >> 4, col = tx & 15;
    int oh = oh0 + row, ow = ow0 + col;
    int khp = (oh + 1) & 1, kwp = (ow + 1) & 1;
    int ih0 = (oh0 >> 1) - 1, iw0 = (ow0 >> 1) - 1;
    float acc[3] = {0.f, 0.f, 0.f};

#pragma unroll 1
    for (int ci0 = 0; ci0 < Cin; ci0 += CI) {
        __syncthreads();
#pragma unroll 1
        for (int idx = tx; idx < CI * 100; idx += 256) {
            int ci  = idx / 100;
            int rem = idx - ci * 100;
            int lh  = rem / 10, lw = rem - lh * 10;
            int ih  = ih0 + lh, iw = iw0 + lw;
            float v = 0.f;
            if ((unsigned)ih < (unsigned)Hin && (unsigned)iw < (unsigned)Win) {
                int cg = ci0 + ci;
                v = in[(((size_t)n * Cin + cg) * Hin + ih) * Win + iw];
                v = bnrelu_apply(v, bmean[cg], br[cg], bg[cg], bb[cg]);
            }
            s_in[idx] = v;
        }
#pragma unroll 1
        for (int idx = tx; idx < CI * 48; idx += 256) {
            int ci  = idx / 48;
            int rem = idx - ci * 48;
            s_w[idx] = wgt[(size_t)(ci0 + ci) * 48 + rem];
        }
        __syncthreads();
#pragma unroll 2
        for (int ci = 0; ci < CI; ++ci) {
#pragma unroll
            for (int a = 0; a < 2; ++a) {
                int ihl = ((oh + 1) >> 1) - a - ih0;
                int kh  = khp + 2 * a;
#pragma unroll
                for (int b = 0; b < 2; ++b) {
                    int iwl = ((ow + 1) >> 1) - b - iw0;
                    int kw  = kwp + 2 * b;
                    float iv = s_in[ci * 100 + ihl * 10 + iwl];
#pragma unroll
                    for (int co = 0; co < 3; ++co)
                        acc[co] = fmaf(s_w[ci * 48 + co * 16 + kh * 4 + kw], iv, acc[co]);
                }
            }
        }
    }
#pragma unroll
    for (int co = 0; co < 3; ++co)
        out[(((size_t)n * 3 + co) * Hout + oh) * Wout + ow] = __fadd_rn(acc[co], bias[co]);
}

// ---------------- VQ (reference fp32 numerics, unchanged) ----------------
__global__ void cnorm_kernel(const float* __restrict__ cb, float* __restrict__ cn)
{
    int k = blockIdx.x * blockDim.x + threadIdx.x;
    if (k < 512) {
        const float* p = cb + (size_t)k * 256;
        float acc = 0.f;
#pragma unroll 4
        for (int d = 0; d < 256; ++d)
            acc = __fadd_rn(acc, __fmul_rn(p[d], p[d]));
        cn[k] = acc;
    }
}

__global__ void __launch_bounds__(256)
vq_argmin_kernel(const float* __restrict__ z, const float* __restrict__ cb,
                 const float* __restrict__ cn, int* __restrict__ q)
{
    __shared__ float s_z[32 * 257];
    __shared__ float s_Z[32];
    __shared__ float s_bd[256];
    __shared__ int   s_bi[256];
    int nh = blockIdx.x;
    int n = nh >> 5, h = nh & 31;
    int tx = threadIdx.x;
    size_t zb = (size_t)n * 262144 + (size_t)h * 32;
#pragma unroll 1
    for (int idx = tx; idx < 256 * 32; idx += 256) {
        int d = idx >> 5, w = idx & 31;
        s_z[w * 257 + d] = 2.0f * z[zb + (size_t)d * 1024 + w];
    }
    __syncthreads();
    if (tx < 32) {
        const float* zr = s_z + tx * 257;
        float acc = 0.f;
#pragma unroll 4
        for (int d = 0; d < 256; ++d) {
            float zv = 0.5f * zr[d];
            acc = __fadd_rn(acc, __fmul_rn(zv, zv));
        }
        s_Z[tx] = acc;
    }
    __syncthreads();

    int m = tx & 31, g = tx >> 5;
    const float* zr = s_z + m * 257;
    float Zm = s_Z[m];
    float best = 3.4028235e38f;
    int bi = 0;
#pragma unroll 1
    for (int t = 0; t < 64; t += 2) {
        int k0 = g + 8 * t;
        int k1 = k0 + 8;
        const float* c0 = cb + (size_t)k0 * 256;
        const float* c1 = cb + (size_t)k1 * 256;
        float A = 0.f, B = 0.f;
#pragma unroll 4
        for (int d = 0; d < 256; ++d) {
            float zv = zr[d];
            A = fmaf(zv, c0[d], A);
            B = fmaf(zv, c1[d], B);
        }
        float t0 = __fadd_rn(__fsub_rn(Zm, A), cn[k0]);
        float t1 = __fadd_rn(__fsub_rn(Zm, B), cn[k1]);
        if (t0 < best) { best = t0; bi = k0; }
        if (t1 < best) { best = t1; bi = k1; }
    }
    s_bd[g * 32 + m] = best;
    s_bi[g * 32 + m] = bi;
    __syncthreads();
    if (tx < 32) {
        float bb = s_bd[tx];
        int   ii = s_bi[tx];
#pragma unroll
        for (int gg = 1; gg < 8; ++gg) {
            float dd = s_bd[gg * 32 + tx];
            int   jj = s_bi[gg * 32 + tx];
            if (dd < bb || (dd == bb && jj < ii)) { bb = dd; ii = jj; }
        }
        q[nh * 32 + tx] = ii;
    }
}

__global__ void vq_gather_kernel(const int* __restrict__ q, const float* __restrict__ cb,
                                 float* __restrict__ zq)
{
    __shared__ int s_q[32];
    int nh = blockIdx.x;
    int n = nh >> 5, h = nh & 31;
    int tx = threadIdx.x;
    if (tx < 32) s_q[tx] = q[nh * 32 + tx];
    __syncthreads();
    size_t zb = (size_t)n * 262144 + (size_t)h * 32;
#pragma unroll 1
    for (int idx = tx; idx < 256 * 32; idx += 256) {
        int d = idx >> 5, w = idx & 31;
        zq[zb + (size_t)d * 1024 + w] = cb[(size_t)s_q[w] * 256 + d];
    }
}

// ---------------- host ----------------
static void run_resblock_enc(const float* X, float* T, float* Y,
                             const float* bn1g, const float* bn1b,
                             const float* c3w, const float* c3b,
                             const float* bn2g, const float* bn2b,
                             const float* c1w, const float* c1b,
                             float* mn, float* rr)
{
    bn_stats_kernel<<<256, 256>>>(X, mn, rr, 16, 256, 1024);
    conv3x3_v2<<<dim3(16 * 8, 8), 256>>>(X, c3w, c3b, mn, rr, bn1g, bn1b, T);
    bn_stats_kernel<<<256, 256>>>(T, mn, rr, 16, 256, 1024);
    conv1x1_v2<<<dim3(16 * 8, 4), 256>>>(T, c1w, c1b, mn, rr, bn2g, bn2b, X, Y);
}

static void run_resblock_dec(const float* X, float* T, float* Y,
                             const float* bn1g, const float* bn1b,
                             const float* c3w, const float* c3b,
                             const float* bn2g, const float* bn2b,
                             const float* c1w, const float* c1b,
                             float* mn, float* rr)
{
    bn_stats_kernel<<<256, 256>>>(X, mn, rr, 16, 256, 1024);
    conv_mma<true, false><<<dim3(16 * 16, 2), 256>>>(X, c3w, c3b, mn, rr, bn1g, bn1b,
                                                     nullptr, T);
    bn_stats_kernel<<<256, 256>>>(T, mn, rr, 16, 256, 1024);
    conv_mma<false, true><<<dim3(16 * 16, 2), 256>>>(T, c1w, c1b, mn, rr, bn2g, bn2b,
                                                     X, Y);
}

extern "C" void kernel_launch(void* const* d_in, const int* in_sizes, int n_in,
                              void* d_out, int out_size)
{
    (void)in_sizes; (void)n_in; (void)out_size;
    const float* x        = (const float*)d_in[0];
    const float* ec1_w    = (const float*)d_in[1];
    const float* ec1_b    = (const float*)d_in[2];
    const float* ebn1_g   = (const float*)d_in[3];
    const float* ebn1_b   = (const float*)d_in[4];
    const float* ec2_w    = (const float*)d_in[5];
    const float* ec2_b    = (const float*)d_in[6];
    const float* rb_bn1_g = (const float*)d_in[7];
    const float* rb_bn1_b = (const float*)d_in[8];
    const float* rb_c3_w  = (const float*)d_in[9];
    const float* rb_c3_b  = (const float*)d_in[10];
    const float* rb_bn2_g = (const float*)d_in[11];
    const float* rb_bn2_b = (const float*)d_in[12];
    const float* rb_c1_w  = (const float*)d_in[13];
    const float* rb_c1_b  = (const float*)d_in[14];
    const float* dbn1_g   = (const float*)d_in[15];
    const float* dbn1_b   = (const float*)d_in[16];
    const float* dct1_w   = (const float*)d_in[17];
    const float* dct1_b   = (const float*)d_in[18];
    const float* dbn2_g   = (const float*)d_in[19];
    const float* dbn2_b   = (const float*)d_in[20];
    const float* dct2_w   = (const float*)d_in[21];
    const float* dct2_b   = (const float*)d_in[22];
    const float* codebook = (const float*)d_in[23];

    float *A64, *Ba, *Bb, *Bc, *mn, *rr, *cn;
    int* q;
    cudaGetSymbolAddress((void**)&A64, g_A64);
    cudaGetSymbolAddress((void**)&Ba,  g_B32a);
    cudaGetSymbolAddress((void**)&Bb,  g_B32b);
    cudaGetSymbolAddress((void**)&Bc,  g_B32c);
    cudaGetSymbolAddress((void**)&mn,  g_mean);
    cudaGetSymbolAddress((void**)&rr,  g_r);
    cudaGetSymbolAddress((void**)&cn,  g_cnorm);
    cudaGetSymbolAddress((void**)&q,   g_q);

    float* out   = (float*)d_out;
    float* x_rec = out;
    float* z_e   = out + 786432;
    float* z_q   = z_e + 4194304;

    // encoder (exact fp32 — feeds z_e / z_q, must stay bitwise stable)
    conv4x4s2_v2<false><<<dim3(16 * 32, 8), 256>>>(
        x, ec1_w, ec1_b, nullptr, nullptr, nullptr, nullptr, A64,
        16, 3, 128, 128, 256, 64, 64);
    bn_stats_kernel<<<256, 256>>>(A64, mn, rr, 16, 256, 4096);
    conv4x4s2_v2<true><<<dim3(16 * 8, 8), 256>>>(
        A64, ec2_w, ec2_b, mn, rr, ebn1_g, ebn1_b, Ba,
        16, 256, 64, 64, 256, 32, 32);

    const size_t W3 = (size_t)256 * 256 * 9;
    const size_t W1 = (size_t)256 * 256;
    run_resblock_enc(Ba, Bb, Bc, rb_bn1_g + 0, rb_bn1_b + 0, rb_c3_w + 0 * W3, rb_c3_b + 0,
                     rb_bn2_g + 0, rb_bn2_b + 0, rb_c1_w + 0 * W1, rb_c1_b + 0, mn, rr);
    run_resblock_enc(Bc, Bb, z_e, rb_bn1_g + 256, rb_bn1_b + 256, rb_c3_w + 1 * W3, rb_c3_b + 256,
                     rb_bn2_g + 256, rb_bn2_b + 256, rb_c1_w + 1 * W1, rb_c1_b + 256, mn, rr);

    // VQ (exact fp32, unchanged)
    cnorm_kernel<<<2, 256>>>(codebook, cn);
    vq_argmin_kernel<<<512, 256>>>(z_e, codebook, cn, q);
    vq_gather_kernel<<<512, 256>>>(q, codebook, z_q);

    // decoder (x_rec tolerance 1e-3 — bf16 mma.sync 2-split resblocks)
    run_resblock_dec(z_e, Ba, Bb, rb_bn1_g + 512, rb_bn1_b + 512, rb_c3_w + 2 * W3, rb_c3_b + 512,
                     rb_bn2_g + 512, rb_bn2_b + 512, rb_c1_w + 2 * W1, rb_c1_b + 512, mn, rr);
    run_resblock_dec(Bb, Bc, Ba, rb_bn1_g + 768, rb_bn1_b + 768, rb_c3_w + 3 * W3, rb_c3_b + 768,
                     rb_bn2_g + 768, rb_bn2_b + 768, rb_c1_w + 3 * W1, rb_c1_b + 768, mn, rr);

    bn_stats_kernel<<<256, 256>>>(Ba, mn, rr, 16, 256, 1024);
    convT4x4_v2<<<dim3(16 * 32, 4), 256>>>(
        Ba, dct1_w, dct1_b, mn, rr, dbn1_g, dbn1_b, A64,
        16, 256, 32, 32, 256, 64, 64);
    bn_stats_kernel<<<256, 256>>>(A64, mn, rr, 16, 256, 4096);
    convT_out_kernel<<<16 * 64, 256>>>(
        A64, dct2_w, dct2_b, mn, rr, dbn2_g, dbn2_b, x_rec,
        16, 256, 64, 64, 128, 128);
}

// round 17
// speedup vs baseline: 1.1088x; 1.1088x over previous
#include <cuda_runtime.h>
#include <cuda_bf16.h>
#include <cstdint>

#define BN_EPS 1e-5f

static constexpr size_t SZ64 = (size_t)16 * 256 * 64 * 64;
static constexpr size_t SZ32 = (size_t)16 * 256 * 32 * 32;

__device__ float g_A64[SZ64];
__device__ float g_B32a[SZ32];
__device__ float g_B32b[SZ32];
__device__ float g_B32c[SZ32];
__device__ float g_mean[256];
__device__ float g_r[256];
__device__ float g_cnorm[512];
__device__ int   g_q[16384];
// pre-split bf16 planes (decoder MMA path)
__device__ __nv_bfloat16 g_wh[256 * 2304];
__device__ __nv_bfloat16 g_wl[256 * 2304];
__device__ __nv_bfloat16 g_xh[(size_t)16 * 256 * 1024];
__device__ __nv_bfloat16 g_xl[(size_t)16 * 256 * 1024];

// ---------------- portable tensor-core helpers (sm_80+ PTX, legal on sm_103) --------
__device__ __forceinline__ uint32_t smem_u32(const void* p) {
    uint32_t a;
    asm("{ .reg .u64 t; cvta.to.shared.u64 t, %1; cvt.u32.u64 %0, t; }" : "=r"(a) : "l"(p));
    return a;
}
__device__ __forceinline__ void ldsm4(uint32_t* r, uint32_t addr) {
    asm volatile("ldmatrix.sync.aligned.m8n8.x4.shared.b16 {%0,%1,%2,%3}, [%4];"
                 : "=r"(r[0]), "=r"(r[1]), "=r"(r[2]), "=r"(r[3]) : "r"(addr));
}
__device__ __forceinline__ void ldsm2(uint32_t* r, uint32_t addr) {
    asm volatile("ldmatrix.sync.aligned.m8n8.x2.shared.b16 {%0,%1}, [%2];"
                 : "=r"(r[0]), "=r"(r[1]) : "r"(addr));
}
__device__ __forceinline__ void mma16816(float* d, const uint32_t* a, const uint32_t* b) {
    asm volatile(
        "mma.sync.aligned.m16n8k16.row.col.f32.bf16.bf16.f32 "
        "{%0,%1,%2,%3}, {%4,%5,%6,%7}, {%8,%9}, {%0,%1,%2,%3};"
        : "+f"(d[0]), "+f"(d[1]), "+f"(d[2]), "+f"(d[3])
        : "r"(a[0]), "r"(a[1]), "r"(a[2]), "r"(a[3]), "r"(b[0]), "r"(b[1]));
}

// ---- BN batch stats ----
__global__ void bn_stats_kernel(const float* __restrict__ x,
                                float* __restrict__ mean_out,
                                float* __restrict__ r_out,
                                int N, int C, int HW)
{
    int c = blockIdx.x;
    int tx = threadIdx.x;
    __shared__ float red[256];
    __shared__ float s_m;
    float inv = 1.f / (float)(N * HW);

    float s = 0.f;
    for (int n = 0; n < N; ++n) {
        const float* p = x + ((size_t)n * C + c) * HW;
        for (int i = tx; i < HW; i += 256) s += p[i];
    }
    red[tx] = s;
    __syncthreads();
    for (int o = 128; o > 0; o >>= 1) {
        if (tx < o) red[tx] += red[tx + o];
        __syncthreads();
    }
    if (tx == 0) s_m = red[0] * inv;
    __syncthreads();
    float m = s_m;

    float s2 = 0.f;
    for (int n = 0; n < N; ++n) {
        const float* p = x + ((size_t)n * C + c) * HW;
        for (int i = tx; i < HW; i += 256) {
            float d = __fsub_rn(p[i], m);
            s2 += __fmul_rn(d, d);
        }
    }
    red[tx] = s2;
    __syncthreads();
    for (int o = 128; o > 0; o >>= 1) {
        if (tx < o) red[tx] += red[tx + o];
        __syncthreads();
    }
    if (tx == 0) {
        float var = red[0] * inv;
        mean_out[c] = m;
        r_out[c] = __fdiv_rn(1.0f, __fsqrt_rn(__fadd_rn(var, BN_EPS)));
    }
}

__device__ __forceinline__ float bnrelu_apply(float v, float m, float r, float g, float b)
{
    float t = __fsub_rn(v, m);
    t = __fmul_rn(t, r);
    t = __fmul_rn(t, g);
    t = __fadd_rn(t, b);
    return fmaxf(t, 0.f);
}

// ---------------- pre-split kernels (decoder MMA path) ----------------
__global__ void wsplit_kernel(const float* __restrict__ w, int nelem,
                              __nv_bfloat16* __restrict__ wh, __nv_bfloat16* __restrict__ wl)
{
    for (int i = blockIdx.x * 256 + threadIdx.x; i < nelem; i += gridDim.x * 256) {
        float v = w[i];
        __nv_bfloat16 h = __float2bfloat16(v);
        wh[i] = h;
        wl[i] = __float2bfloat16(__fsub_rn(v, __bfloat162float(h)));
    }
}

// bnrelu + bf16 split of a [16,256,32,32] activation tensor
__global__ void asplit_kernel(const float* __restrict__ x,
                              const float* __restrict__ mean, const float* __restrict__ rr,
                              const float* __restrict__ gg, const float* __restrict__ bb,
                              __nv_bfloat16* __restrict__ xh, __nv_bfloat16* __restrict__ xl)
{
    size_t i = (size_t)blockIdx.x * 256 + threadIdx.x;
    int c = (int)((i >> 10) & 255);
    float v = bnrelu_apply(x[i], mean[c], rr[c], gg[c], bb[c]);
    __nv_bfloat16 h = __float2bfloat16(v);
    xh[i] = h;
    xl[i] = __float2bfloat16(__fsub_rn(v, __bfloat162float(h)));
}

// ============ DECODER resblock convs: mma.sync on pre-split bf16 planes =============
// Block: 128 co x 128 px (4 oh rows), 8 warps 4(M)x2(N); warp tile 32co x 64px.
// K chunks of 32; fragment layouts identical to validated R16 kernel.
template<bool IS3X3, bool ADDRES>
__global__ void __launch_bounds__(256, 2)
conv_mma2(const __nv_bfloat16* __restrict__ xh, const __nv_bfloat16* __restrict__ xl,
          const __nv_bfloat16* __restrict__ wh, const __nv_bfloat16* __restrict__ wl,
          const float* __restrict__ bias, const float* __restrict__ res,
          float* __restrict__ out)
{
    constexpr int KTOT = IS3X3 ? 2304 : 256;
    constexpr int NCH  = KTOT / 32;
    constexpr int AST  = 40;
    __shared__ __nv_bfloat16 sAh[128 * AST], sAl[128 * AST];
    __shared__ __nv_bfloat16 sBh[128 * AST], sBl[128 * AST];

    int tx = threadIdx.x, wid = tx >> 5, lane = tx & 31;
    int n = blockIdx.x >> 3, pxt = blockIdx.x & 7;
    int oh0 = pxt * 4;
    int co0 = blockIdx.y * 128;
    int wm = (wid >> 1) * 32;
    int wn = (wid & 1) * 64;

    uint32_t bAh = smem_u32(sAh), bAl = smem_u32(sAl);
    uint32_t bBh = smem_u32(sBh), bBl = smem_u32(sBl);

    float d[2][8][4];
#pragma unroll
    for (int mi = 0; mi < 2; ++mi)
#pragma unroll
        for (int ni = 0; ni < 8; ++ni)
#pragma unroll
            for (int e = 0; e < 4; ++e) d[mi][ni][e] = 0.f;

#pragma unroll 1
    for (int c = 0; c < NCH; ++c) {
        __syncthreads();
        // stage A: 128co x 32k, pure bf16 copies from pre-split weights
#pragma unroll 1
        for (int idx = tx; idx < 4096; idx += 256) {
            int co = idx >> 5, j = idx & 31;
            size_t g = (size_t)(co0 + co) * KTOT + c * 32 + j;
            sAh[co * AST + j] = wh[g];
            sAl[co * AST + j] = wl[g];
        }
        // stage B: 128px x 32k (im2col gather for 3x3, direct for 1x1)
#pragma unroll 1
        for (int idx = tx; idx < 4096; idx += 256) {
            int p = idx >> 5, j = idx & 31, k = c * 32 + j;
            int oh = oh0 + (p >> 5), ow = p & 31;
            __nv_bfloat16 h, l;
            if (IS3X3) {
                int ci = k / 9, t = k - ci * 9, kh = t / 3, kw = t - kh * 3;
                int ih = oh + kh - 1, iw = ow + kw - 1;
                if ((unsigned)ih < 32u && (unsigned)iw < 32u) {
                    size_t g = ((size_t)n * 256 + ci) * 1024 + ih * 32 + iw;
                    h = xh[g]; l = xl[g];
                } else {
                    h = __float2bfloat16(0.f); l = __float2bfloat16(0.f);
                }
            } else {
                size_t g = ((size_t)n * 256 + k) * 1024 + oh * 32 + ow;
                h = xh[g]; l = xl[g];
            }
            sBh[p * AST + j] = h;
            sBl[p * AST + j] = l;
        }
        __syncthreads();
#pragma unroll
        for (int ks = 0; ks < 2; ++ks) {
            int k0 = ks * 16;
            uint32_t Ah[2][4], Al[2][4];
            int arow = lane & 15;
            int akof = k0 + (lane >> 4) * 8;
#pragma unroll
            for (int mi = 0; mi < 2; ++mi) {
                uint32_t off = (uint32_t)((wm + mi * 16 + arow) * AST + akof) * 2;
                ldsm4(Ah[mi], bAh + off);
                ldsm4(Al[mi], bAl + off);
            }
            int brow = lane & 7;
            int bkof = k0 + ((lane >> 3) & 1) * 8;
#pragma unroll
            for (int ni = 0; ni < 8; ++ni) {
                uint32_t off = (uint32_t)((wn + ni * 8 + brow) * AST + bkof) * 2;
                uint32_t Bh[2], Bl[2];
                ldsm2(Bh, bBh + off);
                ldsm2(Bl, bBl + off);
#pragma unroll
                for (int mi = 0; mi < 2; ++mi) {
                    mma16816(d[mi][ni], Ah[mi], Bh);
                    mma16816(d[mi][ni], Ah[mi], Bl);
                    mma16816(d[mi][ni], Al[mi], Bh);
                }
            }
        }
    }
    int r0 = lane >> 2, cpair = 2 * (lane & 3);
#pragma unroll
    for (int mi = 0; mi < 2; ++mi) {
#pragma unroll
        for (int ni = 0; ni < 8; ++ni) {
            int row = wm + mi * 16 + r0;
            int col = wn + ni * 8 + cpair;
            int oh = oh0 + (col >> 5), ow = col & 31;
            int coA = co0 + row, coB = co0 + row + 8;
            float bvA = bias[coA], bvB = bias[coB];
            size_t pA = (((size_t)n * 256 + coA) * 32 + oh) * 32 + ow;
            size_t pB = (((size_t)n * 256 + coB) * 32 + oh) * 32 + ow;
            float v0 = __fadd_rn(d[mi][ni][0], bvA);
            float v1 = __fadd_rn(d[mi][ni][1], bvA);
            float v2 = __fadd_rn(d[mi][ni][2], bvB);
            float v3 = __fadd_rn(d[mi][ni][3], bvB);
            if (ADDRES) {
                v0 = __fadd_rn(v0, res[pA]);
                v1 = __fadd_rn(v1, res[pA + 1]);
                v2 = __fadd_rn(v2, res[pB]);
                v3 = __fadd_rn(v3, res[pB + 1]);
            }
            out[pA]     = v0;
            out[pA + 1] = v1;
            out[pB]     = v2;
            out[pB + 1] = v3;
        }
    }
}

// ================= ENCODER conv 3x3 (exact fp32, unchanged) =================
__global__ void __launch_bounds__(256)
conv3x3_v2(const float* __restrict__ in, const float* __restrict__ wgt,
           const float* __restrict__ bias,
           const float* __restrict__ bmean, const float* __restrict__ br,
           const float* __restrict__ bg, const float* __restrict__ bb,
           float* __restrict__ out)
{
    constexpr int CI = 8, KC = 72, WS = 73, PH = 10, PW = 18;
    __shared__ float s_in[CI * PH * PW];
    __shared__ float s_w[32 * WS];

    int n   = blockIdx.x >> 3;
    int t   = blockIdx.x & 7;
    int oh0 = (t >> 1) * 8, ow0 = (t & 1) * 16;
    int co0 = blockIdx.y * 32;
    int tx = threadIdx.x, c = tx & 15, r = tx >> 4;
    int row = r >> 1, owl0 = (r & 1) * 8;

    float acc[2][8];
#pragma unroll
    for (int j = 0; j < 2; ++j)
#pragma unroll
        for (int p = 0; p < 8; ++p) acc[j][p] = 0.f;

    int ihb = oh0 - 1, iwb = ow0 - 1;

#pragma unroll 1
    for (int ci0 = 0; ci0 < 256; ci0 += CI) {
        __syncthreads();
#pragma unroll 1
        for (int idx = tx; idx < CI * PH * PW; idx += 256) {
            int ci = idx / (PH * PW);
            int rem = idx - ci * (PH * PW);
            int lh = rem / PW, lw = rem - lh * PW;
            int ih = ihb + lh, iw = iwb + lw;
            int cg = ci0 + ci;
            float v = 0.f;
            if ((unsigned)ih < 32u && (unsigned)iw < 32u) {
                v = in[(((size_t)n * 256 + cg) * 32 + ih) * 32 + iw];
                v = bnrelu_apply(v, bmean[cg], br[cg], bg[cg], bb[cg]);
            }
            s_in[idx] = v;
        }
#pragma unroll 1
        for (int idx = tx; idx < 32 * KC; idx += 256) {
            int co = idx / KC, k = idx - co * KC;
            int ci = k / 9, kk = k - ci * 9;
            s_w[co * WS + k] = wgt[((size_t)(co0 + co) * 256 + ci0 + ci) * 9 + kk];
        }
        __syncthreads();
#pragma unroll
        for (int ci = 0; ci < CI; ++ci) {
#pragma unroll
            for (int kh = 0; kh < 3; ++kh) {
                const float* bp = &s_in[ci * PH * PW + (row + kh) * PW + owl0];
                float v[10];
#pragma unroll
                for (int q = 0; q < 5; ++q) {
                    float2 Q = *(const float2*)(bp + 2 * q);
                    v[2 * q] = Q.x; v[2 * q + 1] = Q.y;
                }
                int kbase = ci * 9 + kh * 3;
#pragma unroll
                for (int kw = 0; kw < 3; ++kw) {
                    int k = kbase + kw;
                    float wv[2];
#pragma unroll
                    for (int j = 0; j < 2; ++j) wv[j] = s_w[(c + 16 * j) * WS + k];
#pragma unroll
                    for (int j = 0; j < 2; ++j)
#pragma unroll
                        for (int p = 0; p < 8; ++p)
                            acc[j][p] = fmaf(wv[j], v[kw + p], acc[j][p]);
                }
            }
        }
    }
    int oh = oh0 + row;
#pragma unroll
    for (int j = 0; j < 2; ++j) {
        int co = co0 + c + 16 * j;
        float bv = bias[co];
        size_t base = (((size_t)n * 256 + co) * 32 + oh) * 32 + ow0 + owl0;
#pragma unroll
        for (int p = 0; p < 8; ++p)
            out[base + p] = __fadd_rn(acc[j][p], bv);
    }
}

// ================= ENCODER conv 1x1 (exact fp32, unchanged) =================
__global__ void __launch_bounds__(256)
conv1x1_v2(const float* __restrict__ in, const float* __restrict__ wgt,
           const float* __restrict__ bias,
           const float* __restrict__ bmean, const float* __restrict__ br,
           const float* __restrict__ bg, const float* __restrict__ bb,
           const float* __restrict__ res, float* __restrict__ out)
{
    constexpr int CI = 32, WS = 33;
    __shared__ float s_in[CI * 128];
    __shared__ float s_w[64 * WS];

    int n   = blockIdx.x >> 3;
    int t   = blockIdx.x & 7;
    int oh0 = (t >> 1) * 8, ow0 = (t & 1) * 16;
    int co0 = blockIdx.y * 64;
    int tx = threadIdx.x, c = tx & 15, r = tx >> 4;
    int row = r >> 1, owl0 = (r & 1) * 8;

    float acc[4][8];
#pragma unroll
    for (int j = 0; j < 4; ++j)
#pragma unroll
        for (int p = 0; p < 8; ++p) acc[j][p] = 0.f;

#pragma unroll 1
    for (int ci0 = 0; ci0 < 256; ci0 += CI) {
        __syncthreads();
#pragma unroll 1
        for (int idx = tx; idx < CI * 128; idx += 256) {
            int ci = idx >> 7, rem = idx & 127;
            int ih = oh0 + (rem >> 4), iw = ow0 + (rem & 15);
            int cg = ci0 + ci;
            float v = in[(((size_t)n * 256 + cg) * 32 + ih) * 32 + iw];
            s_in[idx] = bnrelu_apply(v, bmean[cg], br[cg], bg[cg], bb[cg]);
        }
#pragma unroll 1
        for (int idx = tx; idx < 64 * CI; idx += 256) {
            int co = idx / CI, k = idx - co * CI;
            s_w[co * WS + k] = wgt[(size_t)(co0 + co) * 256 + ci0 + k];
        }
        __syncthreads();
#pragma unroll 4
        for (int ci = 0; ci < CI; ++ci) {
            const float* bp = &s_in[ci * 128 + row * 16 + owl0];
            float v[8];
#pragma unroll
            for (int q = 0; q < 4; ++q) {
                float2 Q = *(const float2*)(bp + 2 * q);
                v[2 * q] = Q.x; v[2 * q + 1] = Q.y;
            }
            float wv[4];
#pragma unroll
            for (int j = 0; j < 4; ++j) wv[j] = s_w[(c + 16 * j) * WS + ci];
#pragma unroll
            for (int j = 0; j < 4; ++j)
#pragma unroll
                for (int p = 0; p < 8; ++p)
                    acc[j][p] = fmaf(wv[j], v[p], acc[j][p]);
        }
    }
    int oh = oh0 + row;
#pragma unroll
    for (int j = 0; j < 4; ++j) {
        int co = co0 + c + 16 * j;
        float bv = bias[co];
        size_t base = (((size_t)n * 256 + co) * 32 + oh) * 32 + ow0 + owl0;
#pragma unroll
        for (int p = 0; p < 8; ++p)
            out[base + p] = __fadd_rn(__fadd_rn(acc[j][p], bv), res[base + p]);
    }
}

// ================= conv 4x4 s2 p1 (ec1/ec2, exact fp32) =================
template<bool BNRELU>
__global__ void __launch_bounds__(256)
conv4x4s2_v2(const float* __restrict__ in, const float* __restrict__ wgt,
             const float* __restrict__ bias,
             const float* __restrict__ bmean, const float* __restrict__ br,
             const float* __restrict__ bg, const float* __restrict__ bb,
             float* __restrict__ out,
             int N, int Cin, int Hin, int Win, int Cout, int Hout, int Wout)
{
    constexpr int CI = 4, KC = 64, WS = 65, PH = 18, PW = 34;
    __shared__ float s_in[CI * PH * PW];
    __shared__ float s_w[32 * WS];

    int tilesW = Wout / 16, tilesH = Hout / 8;
    int tpi = tilesW * tilesH;
    int n = blockIdx.x / tpi;
    int t = blockIdx.x % tpi;
    int oh0 = (t / tilesW) * 8, ow0 = (t % tilesW) * 16;
    int co0 = blockIdx.y * 32;
    int tx = threadIdx.x, c = tx & 15, r = tx >> 4;
    int row = r >> 1, owl0 = (r & 1) * 8;

    float acc[2][8];
#pragma unroll
    for (int j = 0; j < 2; ++j)
#pragma unroll
        for (int p = 0; p < 8; ++p) acc[j][p] = 0.f;

    int ihb = oh0 * 2 - 1, iwb = ow0 * 2 - 1;

#pragma unroll 1
    for (int ci0 = 0; ci0 < Cin; ci0 += CI) {
        __syncthreads();
#pragma unroll 1
        for (int idx = tx; idx < CI * PH * PW; idx += 256) {
            int ci = idx / (PH * PW);
            int rem = idx - ci * (PH * PW);
            int lh = rem / PW, lw = rem - lh * PW;
            int ih = ihb + lh, iw = iwb + lw;
            int cg = ci0 + ci;
            float v = 0.f;
            if (cg < Cin && (unsigned)ih < (unsigned)Hin && (unsigned)iw < (unsigned)Win) {
                v = in[(((size_t)n * Cin + cg) * Hin + ih) * Win + iw];
                if (BNRELU) v = bnrelu_apply(v, bmean[cg], br[cg], bg[cg], bb[cg]);
            }
            s_in[idx] = v;
        }
#pragma unroll 1
        for (int idx = tx; idx < 32 * KC; idx += 256) {
            int co = idx / KC, k = idx - co * KC;
            int ci = k >> 4, kk = k & 15;
            int cg = ci0 + ci;
            s_w[co * WS + k] = (cg < Cin) ? wgt[((size_t)(co0 + co) * Cin + cg) * 16 + kk] : 0.f;
        }
        __syncthreads();
#pragma unroll
        for (int ci = 0; ci < CI; ++ci) {
#pragma unroll
            for (int kh = 0; kh < 4; ++kh) {
                const float* bp = &s_in[ci * PH * PW + (row * 2 + kh) * PW + owl0 * 2];
                float v[18];
#pragma unroll
                for (int q = 0; q < 9; ++q) {
                    float2 Q = *(const float2*)(bp + 2 * q);
                    v[2 * q] = Q.x; v[2 * q + 1] = Q.y;
                }
#pragma unroll
                for (int kw = 0; kw < 4; ++kw) {
                    int k = ci * 16 + kh * 4 + kw;
                    float wv[2];
#pragma unroll
                    for (int j = 0; j < 2; ++j) wv[j] = s_w[(c + 16 * j) * WS + k];
#pragma unroll
                    for (int j = 0; j < 2; ++j)
#pragma unroll
                        for (int p = 0; p < 8; ++p)
                            acc[j][p] = fmaf(wv[j], v[kw + 2 * p], acc[j][p]);
                }
            }
        }
    }
    int oh = oh0 + row;
#pragma unroll
    for (int j = 0; j < 2; ++j) {
        int co = co0 + c + 16 * j;
        float bv = bias[co];
        size_t base = (((size_t)n * Cout + co) * Hout + oh) * Wout + ow0 + owl0;
#pragma unroll
        for (int p = 0; p < 8; ++p)
            out[base + p] = __fadd_rn(acc[j][p], bv);
    }
}

// ================= transposed conv 4x4 s2 p1 (decoder, fp32) =================
__global__ void __launch_bounds__(256)
convT4x4_v2(const float* __restrict__ in, const float* __restrict__ wgt,
            const float* __restrict__ bias,
            const float* __restrict__ bmean, const float* __restrict__ br,
            const float* __restrict__ bg, const float* __restrict__ bb,
            float* __restrict__ out,
            int N, int Cin, int Hin, int Win, int Cout, int Hout, int Wout)
{
    constexpr int CI = 4, KC = 64, WS = 65, PH = 6, PW = 10;
    __shared__ float s_in[CI * PH * PW + 2];
    __shared__ float s_w[64 * WS];

    int tilesW = Wout / 16, tilesH = Hout / 8;
    int tpi = tilesW * tilesH;
    int n = blockIdx.x / tpi;
    int t = blockIdx.x % tpi;
    int oh0 = (t / tilesW) * 8, ow0 = (t % tilesW) * 16;
    int co0 = blockIdx.y * 64;
    int tx = threadIdx.x, c = tx & 15, r = tx >> 4;
    int row = r >> 1, par = r & 1;

    int ih0 = (oh0 >> 1) - 1, iw0 = (ow0 >> 1) - 1;
    int khp = (row + 1) & 1;
    int kwp = 1 - par;

    float acc[4][8];
#pragma unroll
    for (int j = 0; j < 4; ++j)
#pragma unroll
        for (int p = 0; p < 8; ++p) acc[j][p] = 0.f;

#pragma unroll 1
    for (int ci0 = 0; ci0 < Cin; ci0 += CI) {
        __syncthreads();
#pragma unroll 1
        for (int idx = tx; idx < CI * PH * PW; idx += 256) {
            int ci = idx / (PH * PW);
            int rem = idx - ci * (PH * PW);
            int lh = rem / PW, lw = rem - lh * PW;
            int ih = ih0 + lh, iw = iw0 + lw;
            int cg = ci0 + ci;
            float v = 0.f;
            if ((unsigned)ih < (unsigned)Hin && (unsigned)iw < (unsigned)Win) {
                v = in[(((size_t)n * Cin + cg) * Hin + ih) * Win + iw];
                v = bnrelu_apply(v, bmean[cg], br[cg], bg[cg], bb[cg]);
            }
            s_in[idx] = v;
        }
#pragma unroll 1
        for (int idx = tx; idx < 64 * KC; idx += 256) {
            int co = idx / KC, k = idx - co * KC;
            int ci = k >> 4, kk = k & 15;
            s_w[co * WS + k] = wgt[(((size_t)(ci0 + ci) * Cout + co0 + co) << 4) + kk];
        }
        __syncthreads();
#pragma unroll
        for (int ci = 0; ci < CI; ++ci) {
#pragma unroll
            for (int a = 0; a < 2; ++a) {
                int kh  = khp + 2 * a;
                int ihl = ((row + 1) >> 1) + 1 - a;
                int s   = ci * PH * PW + ihl * PW + par;
                int e   = s & ~1;
                int o   = s - e;
                float v[10];
#pragma unroll
                for (int q = 0; q < 5; ++q) {
                    float2 Q = *(const float2*)(&s_in[e + 2 * q]);
                    v[2 * q] = Q.x; v[2 * q + 1] = Q.y;
                }
#pragma unroll
                for (int b = 0; b < 2; ++b) {
                    int kw = kwp + 2 * b;
                    int k  = ci * 16 + kh * 4 + kw;
                    float wv[4];
#pragma unroll
                    for (int j = 0; j < 4; ++j) wv[j] = s_w[(c + 16 * j) * WS + k];
#pragma unroll
                    for (int j = 0; j < 4; ++j)
#pragma unroll
                        for (int p = 0; p < 8; ++p)
                            acc[j][p] = fmaf(wv[j], v[o + 1 - b + p], acc[j][p]);
                }
            }
        }
    }
    int oh = oh0 + row;
#pragma unroll
    for (int j = 0; j < 4; ++j) {
        int co = co0 + c + 16 * j;
        float bv = bias[co];
        size_t base = (((size_t)n * Cout + co) * Hout + oh) * Wout + ow0 + par;
#pragma unroll
        for (int p = 0; p < 8; ++p)
            out[base + 2 * p] = __fadd_rn(acc[j][p], bv);
    }
}

// ---------------- final transposed conv to 3 channels ----------------
__global__ void __launch_bounds__(256)
convT_out_kernel(const float* __restrict__ in, const float* __restrict__ wgt,
                 const float* __restrict__ bias,
                 const float* __restrict__ bmean, const float* __restrict__ br,
                 const float* __restrict__ bg, const float* __restrict__ bb,
                 float* __restrict__ out,
                 int N, int Cin, int Hin, int Win, int Hout, int Wout)
{
    constexpr int CI = 16;
    __shared__ float s_in[CI * 100];
    __shared__ float s_w[CI * 48];
    int tilesW = Wout / 16;
    int tpi = tilesW * (Hout / 16);
    int n  = blockIdx.x / tpi;
    int t  = blockIdx.x % tpi;
    int oh0 = (t / tilesW) * 16, ow0 = (t % tilesW) * 16;
    int tx  = threadIdx.x;
    int row = tx >> 4, col = tx & 15;
    int oh = oh0 + row, ow = ow0 + col;
    int khp = (oh + 1) & 1, kwp = (ow + 1) & 1;
    int ih0 = (oh0 >> 1) - 1, iw0 = (ow0 >> 1) - 1;
    float acc[3] = {0.f, 0.f, 0.f};

#pragma unroll 1
    for (int ci0 = 0; ci0 < Cin; ci0 += CI) {
        __syncthreads();
#pragma unroll 1
        for (int idx = tx; idx < CI * 100; idx += 256) {
            int ci  = idx / 100;
            int rem = idx - ci * 100;
            int lh  = rem / 10, lw = rem - lh * 10;
            int ih  = ih0 + lh, iw = iw0 + lw;
            float v = 0.f;
            if ((unsigned)ih < (unsigned)Hin && (unsigned)iw < (unsigned)Win) {
                int cg = ci0 + ci;
                v = in[(((size_t)n * Cin + cg) * Hin + ih) * Win + iw];
                v = bnrelu_apply(v, bmean[cg], br[cg], bg[cg], bb[cg]);
            }
            s_in[idx] = v;
        }
#pragma unroll 1
        for (int idx = tx; idx < CI * 48; idx += 256) {
            int ci  = idx / 48;
            int rem = idx - ci * 48;
            s_w[idx] = wgt[(size_t)(ci0 + ci) * 48 + rem];
        }
        __syncthreads();
#pragma unroll 2
        for (int ci = 0; ci < CI; ++ci) {
#pragma unroll
            for (int a = 0; a < 2; ++a) {
                int ihl = ((oh + 1) >> 1) - a - ih0;
                int kh  = khp + 2 * a;
#pragma unroll
                for (int b = 0; b < 2; ++b) {
                    int iwl = ((ow + 1) >> 1) - b - iw0;
                    int kw  = kwp + 2 * b;
                    float iv = s_in[ci * 100 + ihl * 10 + iwl];
#pragma unroll
                    for (int co = 0; co < 3; ++co)
                        acc[co] = fmaf(s_w[ci * 48 + co * 16 + kh * 4 + kw], iv, acc[co]);
                }
            }
        }
    }
#pragma unroll
    for (int co = 0; co < 3; ++co)
        out[(((size_t)n * 3 + co) * Hout + oh) * Wout + ow] = __fadd_rn(acc[co], bias[co]);
}

// ---------------- VQ (reference fp32 numerics, unchanged) ----------------
__global__ void cnorm_kernel(const float* __restrict__ cb, float* __restrict__ cn)
{
    int k = blockIdx.x * blockDim.x + threadIdx.x;
    if (k < 512) {
        const float* p = cb + (size_t)k * 256;
        float acc = 0.f;
#pragma unroll 4
        for (int d = 0; d < 256; ++d)
            acc = __fadd_rn(acc, __fmul_rn(p[d], p[d]));
        cn[k] = acc;
    }
}

__global__ void __launch_bounds__(256)
vq_argmin_kernel(const float* __restrict__ z, const float* __restrict__ cb,
                 const float* __restrict__ cn, int* __restrict__ q)
{
    __shared__ float s_z[32 * 257];
    __shared__ float s_Z[32];
    __shared__ float s_bd[256];
    __shared__ int   s_bi[256];
    int nh = blockIdx.x;
    int n = nh >> 5, h = nh & 31;
    int tx = threadIdx.x;
    size_t zb = (size_t)n * 262144 + (size_t)h * 32;
#pragma unroll 1
    for (int idx = tx; idx < 256 * 32; idx += 256) {
        int d = idx >> 5, w = idx & 31;
        s_z[w * 257 + d] = 2.0f * z[zb + (size_t)d * 1024 + w];
    }
    __syncthreads();
    if (tx < 32) {
        const float* zr = s_z + tx * 257;
        float acc = 0.f;
#pragma unroll 4
        for (int d = 0; d < 256; ++d) {
            float zv = 0.5f * zr[d];
            acc = __fadd_rn(acc, __fmul_rn(zv, zv));
        }
        s_Z[tx] = acc;
    }
    __syncthreads();

    int m = tx & 31, g = tx >> 5;
    const float* zr = s_z + m * 257;
    float Zm = s_Z[m];
    float best = 3.4028235e38f;
    int bi = 0;
#pragma unroll 1
    for (int t = 0; t < 64; t += 2) {
        int k0 = g + 8 * t;
        int k1 = k0 + 8;
        const float* c0 = cb + (size_t)k0 * 256;
        const float* c1 = cb + (size_t)k1 * 256;
        float A = 0.f, B = 0.f;
#pragma unroll 4
        for (int d = 0; d < 256; ++d) {
            float zv = zr[d];
            A = fmaf(zv, c0[d], A);
            B = fmaf(zv, c1[d], B);
        }
        float t0 = __fadd_rn(__fsub_rn(Zm, A), cn[k0]);
        float t1 = __fadd_rn(__fsub_rn(Zm, B), cn[k1]);
        if (t0 < best) { best = t0; bi = k0; }
        if (t1 < best) { best = t1; bi = k1; }
    }
    s_bd[g * 32 + m] = best;
    s_bi[g * 32 + m] = bi;
    __syncthreads();
    if (tx < 32) {
        float bb = s_bd[tx];
        int   ii = s_bi[tx];
#pragma unroll
        for (int gg = 1; gg < 8; ++gg) {
            float dd = s_bd[gg * 32 + tx];
            int   jj = s_bi[gg * 32 + tx];
            if (dd < bb || (dd == bb && jj < ii)) { bb = dd; ii = jj; }
        }
        q[nh * 32 + tx] = ii;
    }
}

__global__ void vq_gather_kernel(const int* __restrict__ q, const float* __restrict__ cb,
                                 float* __restrict__ zq)
{
    __shared__ int s_q[32];
    int nh = blockIdx.x;
    int n = nh >> 5, h = nh & 31;
    int tx = threadIdx.x;
    if (tx < 32) s_q[tx] = q[nh * 32 + tx];
    __syncthreads();
    size_t zb = (size_t)n * 262144 + (size_t)h * 32;
#pragma unroll 1
    for (int idx = tx; idx < 256 * 32; idx += 256) {
        int d = idx >> 5, w = idx & 31;
        zq[zb + (size_t)d * 1024 + w] = cb[(size_t)s_q[w] * 256 + d];
    }
}

// ---------------- host ----------------
static void run_resblock_enc(const float* X, float* T, float* Y,
                             const float* bn1g, const float* bn1b,
                             const float* c3w, const float* c3b,
                             const float* bn2g, const float* bn2b,
                             const float* c1w, const float* c1b,
                             float* mn, float* rr)
{
    bn_stats_kernel<<<256, 256>>>(X, mn, rr, 16, 256, 1024);
    conv3x3_v2<<<dim3(16 * 8, 8), 256>>>(X, c3w, c3b, mn, rr, bn1g, bn1b, T);
    bn_stats_kernel<<<256, 256>>>(T, mn, rr, 16, 256, 1024);
    conv1x1_v2<<<dim3(16 * 8, 4), 256>>>(T, c1w, c1b, mn, rr, bn2g, bn2b, X, Y);
}

static void run_resblock_dec(const float* X, float* T, float* Y,
                             const float* bn1g, const float* bn1b,
                             const float* c3w, const float* c3b,
                             const float* bn2g, const float* bn2b,
                             const float* c1w, const float* c1b,
                             float* mn, float* rr,
                             __nv_bfloat16* wh, __nv_bfloat16* wl,
                             __nv_bfloat16* xh, __nv_bfloat16* xl)
{
    bn_stats_kernel<<<256, 256>>>(X, mn, rr, 16, 256, 1024);
    wsplit_kernel<<<2304, 256>>>(c3w, 256 * 2304, wh, wl);
    asplit_kernel<<<16384, 256>>>(X, mn, rr, bn1g, bn1b, xh, xl);
    conv_mma2<true, false><<<dim3(16 * 8, 2), 256>>>(xh, xl, wh, wl, c3b, nullptr, T);
    bn_stats_kernel<<<256, 256>>>(T, mn, rr, 16, 256, 1024);
    wsplit_kernel<<<256, 256>>>(c1w, 256 * 256, wh, wl);
    asplit_kernel<<<16384, 256>>>(T, mn, rr, bn2g, bn2b, xh, xl);
    conv_mma2<false, true><<<dim3(16 * 8, 2), 256>>>(xh, xl, wh, wl, c1b, X, Y);
}

extern "C" void kernel_launch(void* const* d_in, const int* in_sizes, int n_in,
                              void* d_out, int out_size)
{
    (void)in_sizes; (void)n_in; (void)out_size;
    const float* x        = (const float*)d_in[0];
    const float* ec1_w    = (const float*)d_in[1];
    const float* ec1_b    = (const float*)d_in[2];
    const float* ebn1_g   = (const float*)d_in[3];
    const float* ebn1_b   = (const float*)d_in[4];
    const float* ec2_w    = (const float*)d_in[5];
    const float* ec2_b    = (const float*)d_in[6];
    const float* rb_bn1_g = (const float*)d_in[7];
    const float* rb_bn1_b = (const float*)d_in[8];
    const float* rb_c3_w  = (const float*)d_in[9];
    const float* rb_c3_b  = (const float*)d_in[10];
    const float* rb_bn2_g = (const float*)d_in[11];
    const float* rb_bn2_b = (const float*)d_in[12];
    const float* rb_c1_w  = (const float*)d_in[13];
    const float* rb_c1_b  = (const float*)d_in[14];
    const float* dbn1_g   = (const float*)d_in[15];
    const float* dbn1_b   = (const float*)d_in[16];
    const float* dct1_w   = (const float*)d_in[17];
    const float* dct1_b   = (const float*)d_in[18];
    const float* dbn2_g   = (const float*)d_in[19];
    const float* dbn2_b   = (const float*)d_in[20];
    const float* dct2_w   = (const float*)d_in[21];
    const float* dct2_b   = (const float*)d_in[22];
    const float* codebook = (const float*)d_in[23];

    float *A64, *Ba, *Bb, *Bc, *mn, *rr, *cn;
    int* q;
    __nv_bfloat16 *wh, *wl, *xh, *xl;
    cudaGetSymbolAddress((void**)&A64, g_A64);
    cudaGetSymbolAddress((void**)&Ba,  g_B32a);
    cudaGetSymbolAddress((void**)&Bb,  g_B32b);
    cudaGetSymbolAddress((void**)&Bc,  g_B32c);
    cudaGetSymbolAddress((void**)&mn,  g_mean);
    cudaGetSymbolAddress((void**)&rr,  g_r);
    cudaGetSymbolAddress((void**)&cn,  g_cnorm);
    cudaGetSymbolAddress((void**)&q,   g_q);
    cudaGetSymbolAddress((void**)&wh,  g_wh);
    cudaGetSymbolAddress((void**)&wl,  g_wl);
    cudaGetSymbolAddress((void**)&xh,  g_xh);
    cudaGetSymbolAddress((void**)&xl,  g_xl);

    float* out   = (float*)d_out;
    float* x_rec = out;
    float* z_e   = out + 786432;
    float* z_q   = z_e + 4194304;

    // encoder (exact fp32 — feeds z_e / z_q, must stay bitwise stable)
    conv4x4s2_v2<false><<<dim3(16 * 32, 8), 256>>>(
        x, ec1_w, ec1_b, nullptr, nullptr, nullptr, nullptr, A64,
        16, 3, 128, 128, 256, 64, 64);
    bn_stats_kernel<<<256, 256>>>(A64, mn, rr, 16, 256, 4096);
    conv4x4s2_v2<true><<<dim3(16 * 8, 8), 256>>>(
        A64, ec2_w, ec2_b, mn, rr, ebn1_g, ebn1_b, Ba,
        16, 256, 64, 64, 256, 32, 32);

    const size_t W3 = (size_t)256 * 256 * 9;
    const size_t W1 = (size_t)256 * 256;
    run_resblock_enc(Ba, Bb, Bc, rb_bn1_g + 0, rb_bn1_b + 0, rb_c3_w + 0 * W3, rb_c3_b + 0,
                     rb_bn2_g + 0, rb_bn2_b + 0, rb_c1_w + 0 * W1, rb_c1_b + 0, mn, rr);
    run_resblock_enc(Bc, Bb, z_e, rb_bn1_g + 256, rb_bn1_b + 256, rb_c3_w + 1 * W3, rb_c3_b + 256,
                     rb_bn2_g + 256, rb_bn2_b + 256, rb_c1_w + 1 * W1, rb_c1_b + 256, mn, rr);

    // VQ (exact fp32, unchanged)
    cnorm_kernel<<<2, 256>>>(codebook, cn);
    vq_argmin_kernel<<<512, 256>>>(z_e, codebook, cn, q);
    vq_gather_kernel<<<512, 256>>>(q, codebook, z_q);

    // decoder (x_rec tolerance 1e-3 — bf16 mma.sync on pre-split planes)
    run_resblock_dec(z_e, Ba, Bb, rb_bn1_g + 512, rb_bn1_b + 512, rb_c3_w + 2 * W3, rb_c3_b + 512,
                     rb_bn2_g + 512, rb_bn2_b + 512, rb_c1_w + 2 * W1, rb_c1_b + 512, mn, rr,
                     wh, wl, xh, xl);
    run_resblock_dec(Bb, Bc, Ba, rb_bn1_g + 768, rb_bn1_b + 768, rb_c3_w + 3 * W3, rb_c3_b + 768,
                     rb_bn2_g + 768, rb_bn2_b + 768, rb_c1_w + 3 * W1, rb_c1_b + 768, mn, rr,
                     wh, wl, xh, xl);

    bn_stats_kernel<<<256, 256>>>(Ba, mn, rr, 16, 256, 1024);
    convT4x4_v2<<<dim3(16 * 32, 4), 256>>>(
        Ba, dct1_w, dct1_b, mn, rr, dbn1_g, dbn1_b, A64,
        16, 256, 32, 32, 256, 64, 64);
    bn_stats_kernel<<<256, 256>>>(A64, mn, rr, 16, 256, 4096);
    convT_out_kernel<<<16 * 64, 256>>>(
        A64, dct2_w, dct2_b, mn, rr, dbn2_g, dbn2_b, x_rec,
        16, 256, 64, 64, 128, 128);
}